// round 5
// baseline (speedup 1.0000x reference)
#include <cuda_runtime.h>
#include <math.h>

#define NN 50000
#define EO 400000
#define EE 450000
#define F1 512
#define H1 8

// ---------------- scratch (device globals; no runtime allocation) ----------------
__device__ __align__(16) float g_xl1[(size_t)NN * F1];   // 102.4 MB
__device__ __align__(16) float g_xr1[(size_t)NN * F1];   // 102.4 MB
__device__ float        g_ex1[(size_t)EE * H1];          // logits, then exp(logit-max)
__device__ unsigned int g_lmax1[NN * H1];
__device__ float        g_den1[NN * H1];
__device__ int          g_deg[NN];
__device__ int          g_rowptr[NN + 1];
__device__ int          g_cursor[NN];
__device__ int          g_eperm[EE];
__device__ float        g_xl2[NN];
__device__ float        g_xr2[NN];
__device__ float        g_l2[EE];
__device__ unsigned int g_lmax2[NN];
__device__ float        g_den2[NN];

// ordered-uint encoding for float atomicMax
__device__ __forceinline__ unsigned int enc_f(float f) {
    unsigned int u = __float_as_uint(f);
    return (u & 0x80000000u) ? ~u : (u | 0x80000000u);
}
__device__ __forceinline__ float dec_f(unsigned int u) {
    return (u & 0x80000000u) ? __uint_as_float(u & 0x7FFFFFFFu)
                             : __uint_as_float(~u);
}
#define ENC_NEGINF 0x007FFFFFu   // enc(-inf)

// edge_index is int32 on device (JAX default x64-disabled downcasts jnp.int64)
__device__ __forceinline__ int srcof(const int* ei, int e) {
    return (e < EO) ? ei[e] : (e - EO);
}
__device__ __forceinline__ int dstof(const int* ei, int e) {
    return (e < EO) ? ei[EO + e] : (e - EO);
}
__device__ __forceinline__ float lrelu(float v) { return v > 0.0f ? v : 0.2f * v; }

// ---------------- K_init: reset accumulators ----------------
__global__ void k_init() {
    int t = blockIdx.x * blockDim.x + threadIdx.x;
    if (t < NN * H1) { g_lmax1[t] = ENC_NEGINF; g_den1[t] = 0.0f; }
    if (t < NN)      { g_deg[t] = 0; g_lmax2[t] = ENC_NEGINF; g_den2[t] = 0.0f; }
}

// ---------------- K0: degree histogram ----------------
__global__ void k_degree(const int* __restrict__ ei) {
    int e = blockIdx.x * blockDim.x + threadIdx.x;
    if (e >= EE) return;
    atomicAdd(&g_deg[dstof(ei, e)], 1);
}

// ---------------- K1: single-block exclusive scan (rowptr + cursor) ----------------
__global__ void k_scan() {
    __shared__ int sh[1024];
    int t = threadIdx.x;
    int carry = 0;
    for (int base = 0; base < NN; base += 1024) {
        int idx = base + t;
        int v = (idx < NN) ? g_deg[idx] : 0;
        sh[t] = v;
        __syncthreads();
        for (int off = 1; off < 1024; off <<= 1) {
            int add = (t >= off) ? sh[t - off] : 0;
            __syncthreads();
            sh[t] += add;
            __syncthreads();
        }
        int incl = sh[t];
        int total = sh[1023];
        if (idx < NN) {
            g_rowptr[idx + 1] = carry + incl;
            g_cursor[idx]     = carry + incl - v;
        }
        carry += total;
        __syncthreads();
    }
    if (t == 0) g_rowptr[0] = 0;
}

// ---------------- K2: scatter edge ids into CSR (dst-sorted) ----------------
__global__ void k_scatter(const int* __restrict__ ei) {
    int e = blockIdx.x * blockDim.x + threadIdx.x;
    if (e >= EE) return;
    int d = dstof(ei, e);
    int pos = atomicAdd(&g_cursor[d], 1);
    g_eperm[pos] = e;
}

// ---------------- K3: layer-1 linear transforms xl1, xr1 ----------------
__global__ void __launch_bounds__(512) k_lin1(
    const float* __restrict__ x,
    const float* __restrict__ Wl, const float* __restrict__ bl,
    const float* __restrict__ Wr, const float* __restrict__ br) {
    __shared__ float xs[23];
    int i = blockIdx.x;
    int t = threadIdx.x;
    if (t < 23) xs[t] = x[i * 23 + t];
    __syncthreads();
    float al = bl[t], ar = br[t];
#pragma unroll
    for (int k = 0; k < 23; k++) {
        float xv = xs[k];
        al = fmaf(xv, Wl[k * F1 + t], al);
        ar = fmaf(xv, Wr[k * F1 + t], ar);
    }
    g_xl1[(size_t)i * F1 + t] = al;
    g_xr1[(size_t)i * F1 + t] = ar;
}

// ---------------- K4: per-edge logits (warp per edge, dst-sorted order) ----------
// Lane L covers features [L*16, L*16+16) — entirely within head L/4 (head = 64
// features = 4 lanes). Reduce within each 4-lane group; lane 4h writes head h.
__global__ void k_logit1(const int* __restrict__ ei,
                         const float* __restrict__ att) {
    int gw = (blockIdx.x * blockDim.x + threadIdx.x) >> 5;
    if (gw >= EE) return;
    int lane = threadIdx.x & 31;
    int e = g_eperm[gw];
    int s = srcof(ei, e);
    int d = dstof(ei, e);
    const float4* pl = (const float4*)(g_xl1 + (size_t)s * F1 + lane * 16);
    const float4* pr = (const float4*)(g_xr1 + (size_t)d * F1 + lane * 16);
    const float4* pa = (const float4*)(att + lane * 16);
    float acc = 0.0f;
#pragma unroll
    for (int j = 0; j < 4; j++) {
        float4 a = pl[j], b = pr[j], w = pa[j];
        acc = fmaf(lrelu(a.x + b.x), w.x, acc);
        acc = fmaf(lrelu(a.y + b.y), w.y, acc);
        acc = fmaf(lrelu(a.z + b.z), w.z, acc);
        acc = fmaf(lrelu(a.w + b.w), w.w, acc);
    }
    acc += __shfl_down_sync(0xffffffffu, acc, 1);
    acc += __shfl_down_sync(0xffffffffu, acc, 2);
    if ((lane & 3) == 0) {
        int h = lane >> 2;                 // h in [0, 8)
        g_ex1[(size_t)e * H1 + h] = acc;
        atomicMax(&g_lmax1[d * H1 + h], enc_f(acc));
    }
}

// ---------------- K5: exp + denominator ----------------
__global__ void k_denom1(const int* __restrict__ ei) {
    long long t = (long long)blockIdx.x * blockDim.x + threadIdx.x;
    if (t >= (long long)EE * H1) return;
    int e = (int)(t >> 3);
    int h = (int)(t & 7);
    int d = dstof(ei, e);
    float m = dec_f(g_lmax1[d * H1 + h]);
    float ex = expf(g_ex1[t] - m);
    g_ex1[t] = ex;
    atomicAdd(&g_den1[d * H1 + h], ex);
}

// ---------------- K6: per-node aggregation + fused layer-2 projections ----------------
#define CH 64
__global__ void __launch_bounds__(512) k_agg1(
    const int* __restrict__ ei,
    const float* __restrict__ bias1,
    const float* __restrict__ Wl2, const float* __restrict__ bl2,
    const float* __restrict__ Wr2, const float* __restrict__ br2) {
    __shared__ float s_alpha[CH * H1];
    __shared__ int   s_src[CH];
    __shared__ float s_invden[H1];
    __shared__ float s_rl[16], s_rr[16];

    int i = blockIdx.x;
    int t = threadIdx.x;
    int start = g_rowptr[i], end = g_rowptr[i + 1];
    if (t < H1) s_invden[t] = 1.0f / g_den1[i * H1 + t];
    __syncthreads();

    int h = t >> 6;                        // head owning feature t
    float acc = 0.0f;
    for (int c = start; c < end; c += CH) {
        int m = min(CH, end - c);
        if (t < m * H1) {
            int le = t >> 3, hh = t & 7;
            int e = g_eperm[c + le];
            s_alpha[le * H1 + hh] = g_ex1[(size_t)e * H1 + hh] * s_invden[hh];
            if (hh == 0) s_src[le] = srcof(ei, e);
        }
        __syncthreads();
        for (int j = 0; j < m; j++)
            acc = fmaf(s_alpha[j * H1 + h], g_xl1[(size_t)s_src[j] * F1 + t], acc);
        __syncthreads();
    }
    // layer-1 epilogue: + bias, relu; fused layer-2 input projections
    float r  = fmaxf(acc + bias1[t], 0.0f);
    float pl = r * Wl2[t];
    float pr = r * Wr2[t];
#pragma unroll
    for (int off = 16; off > 0; off >>= 1) {
        pl += __shfl_down_sync(0xffffffffu, pl, off);
        pr += __shfl_down_sync(0xffffffffu, pr, off);
    }
    if ((t & 31) == 0) { s_rl[t >> 5] = pl; s_rr[t >> 5] = pr; }
    __syncthreads();
    if (t < 16) {
        pl = s_rl[t]; pr = s_rr[t];
#pragma unroll
        for (int off = 8; off > 0; off >>= 1) {
            pl += __shfl_down_sync(0x0000ffffu, pl, off);
            pr += __shfl_down_sync(0x0000ffffu, pr, off);
        }
        if (t == 0) {
            g_xl2[i] = pl + bl2[0];
            g_xr2[i] = pr + br2[0];
        }
    }
}

// ---------------- K7: layer-2 logits + max ----------------
__global__ void k_logit2(const int* __restrict__ ei,
                         const float* __restrict__ att2) {
    int e = blockIdx.x * blockDim.x + threadIdx.x;
    if (e >= EE) return;
    int s = srcof(ei, e), d = dstof(ei, e);
    float l = lrelu(g_xl2[s] + g_xr2[d]) * att2[0];
    g_l2[e] = l;
    atomicMax(&g_lmax2[d], enc_f(l));
}

// ---------------- K8: layer-2 exp + denom ----------------
__global__ void k_denom2(const int* __restrict__ ei) {
    int e = blockIdx.x * blockDim.x + threadIdx.x;
    if (e >= EE) return;
    int d = dstof(ei, e);
    float ex = expf(g_l2[e] - dec_f(g_lmax2[d]));
    g_l2[e] = ex;
    atomicAdd(&g_den2[d], ex);
}

// ---------------- K9: alpha output ----------------
__global__ void k_alpha2(const int* __restrict__ ei, float* __restrict__ out) {
    int e = blockIdx.x * blockDim.x + threadIdx.x;
    if (e >= EE) return;
    int d = dstof(ei, e);
    out[NN + e] = g_l2[e] / g_den2[d];
}

// ---------------- K10: final per-node output ----------------
__global__ void k_out2(const int* __restrict__ ei,
                       const float* __restrict__ bias2, float* __restrict__ out) {
    int i = blockIdx.x * blockDim.x + threadIdx.x;
    if (i >= NN) return;
    int start = g_rowptr[i], end = g_rowptr[i + 1];
    float sum = 0.0f;
    for (int j = start; j < end; j++) {
        int e = g_eperm[j];
        sum = fmaf(out[NN + e], g_xl2[srcof(ei, e)], sum);
    }
    out[i] = sum + bias2[0];
}

// ---------------- launch ----------------
extern "C" void kernel_launch(void* const* d_in, const int* in_sizes, int n_in,
                              void* d_out, int out_size) {
    const float* x     = (const float*)d_in[0];
    const int*   ei    = (const int*)d_in[1];
    const float* Wl1   = (const float*)d_in[2];
    const float* bl1   = (const float*)d_in[3];
    const float* Wr1   = (const float*)d_in[4];
    const float* br1   = (const float*)d_in[5];
    const float* att1  = (const float*)d_in[6];
    const float* bias1 = (const float*)d_in[7];
    const float* Wl2   = (const float*)d_in[8];
    const float* bl2   = (const float*)d_in[9];
    const float* Wr2   = (const float*)d_in[10];
    const float* br2   = (const float*)d_in[11];
    const float* att2  = (const float*)d_in[12];
    const float* bias2 = (const float*)d_in[13];
    float* out = (float*)d_out;

    k_init<<<(NN * H1 + 255) / 256, 256>>>();
    k_degree<<<(EE + 255) / 256, 256>>>(ei);
    k_scan<<<1, 1024>>>();
    k_scatter<<<(EE + 255) / 256, 256>>>(ei);
    k_lin1<<<NN, 512>>>(x, Wl1, bl1, Wr1, br1);
    k_logit1<<<(EE * 32 + 255) / 256, 256>>>(ei, att1);
    k_denom1<<<(EE * H1 + 255) / 256, 256>>>(ei);
    k_agg1<<<NN, 512>>>(ei, bias1, Wl2, bl2, Wr2, br2);
    k_logit2<<<(EE + 255) / 256, 256>>>(ei, att2);
    k_denom2<<<(EE + 255) / 256, 256>>>(ei);
    k_alpha2<<<(EE + 255) / 256, 256>>>(ei, out);
    k_out2<<<(NN + 255) / 256, 256>>>(ei, bias2, out);
}

// round 7
// speedup vs baseline: 1.4140x; 1.4140x over previous
#include <cuda_runtime.h>
#include <math.h>

#define NN 50000
#define EO 400000
#define EE 450000
#define F1 512
#define H1 8

// ---------------- scratch (device globals; no runtime allocation) ----------------
__device__ __align__(16) float g_xl1[(size_t)NN * F1];   // 102.4 MB
__device__ __align__(16) float g_xr1[(size_t)NN * F1];   // 102.4 MB
__device__ int   g_deg[NN];
__device__ int   g_rowptr[NN + 1];
__device__ int   g_cursor[NN];
__device__ int   g_eperm[EE];
__device__ float g_xl2[NN];
__device__ float g_xr2[NN];
__device__ float g_l2[EE];

__device__ __forceinline__ int srcof(const int* ei, int e) {
    return (e < EO) ? ei[e] : (e - EO);
}
__device__ __forceinline__ int dstof(const int* ei, int e) {
    return (e < EO) ? ei[EO + e] : (e - EO);
}
__device__ __forceinline__ float lrelu(float v) { return v > 0.0f ? v : 0.2f * v; }

// ---------------- K_init: zero degree histogram ----------------
__global__ void k_init0() {
    int t = blockIdx.x * blockDim.x + threadIdx.x;
    if (t < NN) g_deg[t] = 0;
}

// ---------------- K0: degree histogram ----------------
__global__ void k_degree(const int* __restrict__ ei) {
    int e = blockIdx.x * blockDim.x + threadIdx.x;
    if (e >= EE) return;
    atomicAdd(&g_deg[dstof(ei, e)], 1);
}

// ---------------- K1: thread-coarsened exclusive scan (rowptr + cursor) --------
__global__ void k_scan() {
    __shared__ int sh[1024];
    const int PER = (NN + 1023) / 1024;   // 49
    int t = threadIdx.x;
    int base = t * PER;
    int lim = (base < NN) ? min(PER, NN - base) : 0;
    int sum = 0;
    for (int k = 0; k < lim; k++) sum += g_deg[base + k];
    sh[t] = sum;
    __syncthreads();
    for (int off = 1; off < 1024; off <<= 1) {
        int add = (t >= off) ? sh[t - off] : 0;
        __syncthreads();
        sh[t] += add;
        __syncthreads();
    }
    int run = sh[t] - sum;                 // exclusive prefix of this segment
    for (int k = 0; k < lim; k++) {
        int v = g_deg[base + k];
        g_cursor[base + k] = run;
        run += v;
        g_rowptr[base + k + 1] = run;
    }
    if (t == 0) g_rowptr[0] = 0;
}

// ---------------- K2: scatter edge ids into CSR (dst-grouped) ----------------
__global__ void k_scatter(const int* __restrict__ ei) {
    int e = blockIdx.x * blockDim.x + threadIdx.x;
    if (e >= EE) return;
    int pos = atomicAdd(&g_cursor[dstof(ei, e)], 1);
    g_eperm[pos] = e;
}

// ---------------- K3: layer-1 linear transforms (64 nodes/block, W in regs) ----
#define GN 64
__global__ void __launch_bounds__(512) k_lin1(
    const float* __restrict__ x,
    const float* __restrict__ Wl, const float* __restrict__ bl,
    const float* __restrict__ Wr, const float* __restrict__ br) {
    __shared__ float xs[GN][24];
    int t = threadIdx.x;
    int n0 = blockIdx.x * GN;
    for (int idx = t; idx < GN * 23; idx += 512) {
        int n = idx / 23, k = idx % 23;
        int gi = n0 + n;
        xs[n][k] = (gi < NN) ? x[gi * 23 + k] : 0.0f;
    }
    float wl[23], wr[23];
#pragma unroll
    for (int k = 0; k < 23; k++) { wl[k] = Wl[k * F1 + t]; wr[k] = Wr[k * F1 + t]; }
    float bll = bl[t], brr = br[t];
    __syncthreads();
    for (int n = 0; n < GN; n++) {
        int gi = n0 + n;
        if (gi >= NN) break;
        float al = bll, ar = brr;
#pragma unroll
        for (int k = 0; k < 23; k++) {
            float xv = xs[n][k];
            al = fmaf(xv, wl[k], al);
            ar = fmaf(xv, wr[k], ar);
        }
        g_xl1[(size_t)gi * F1 + t] = al;
        g_xr1[(size_t)gi * F1 + t] = ar;
    }
}

// ---------------- K4: fused layer-1 attention (block = dst node) ---------------
// Stages up to 16 xl1[src] rows in smem; logits computed during the load via
// warp-segmented reduction; online softmax; aggregation from staged rows.
// Epilogue: bias+relu, fused layer-2 input projections -> g_xl2/g_xr2.
#define CH1 16
__global__ void __launch_bounds__(512) k_fused1(
    const int* __restrict__ ei,
    const float* __restrict__ att,
    const float* __restrict__ bias1,
    const float* __restrict__ Wl2, const float* __restrict__ bl2,
    const float* __restrict__ Wr2, const float* __restrict__ br2) {
    __shared__ float s_xr[F1];                 // 2 KB
    __shared__ float s_att[F1];                // 2 KB
    __shared__ float s_rows[CH1][F1];          // 32 KB
    __shared__ float s_w[CH1][H1];             // logits -> weights
    __shared__ float s_m[H1], s_den[H1], s_scale[H1];
    __shared__ float s_rl[16], s_rr[16];

    int i = blockIdx.x;
    int t = threadIdx.x;
    int w = t >> 5, lane = t & 31;
    int start = g_rowptr[i], end = g_rowptr[i + 1];

    s_xr[t]  = g_xr1[(size_t)i * F1 + t];
    s_att[t] = att[t];
    if (t < H1) { s_m[t] = -INFINITY; s_den[t] = 0.0f; }
    __syncthreads();

    int h = t >> 6;                            // head owning feature t
    float acc = 0.0f;

    for (int c = start; c < end; c += CH1) {
        int m_e = min(CH1, end - c);
        if (w < m_e) {
            int e = g_eperm[c + w];
            int s = srcof(ei, e);
            const float4* prow = (const float4*)(g_xl1 + (size_t)s * F1);
            float p[4];
#pragma unroll
            for (int k = 0; k < 4; k++) {
                int fi = k * 32 + lane;                  // float4 index
                float4 v  = prow[fi];
                ((float4*)s_rows[w])[fi] = v;
                float4 x4 = ((const float4*)s_xr)[fi];
                float4 a4 = ((const float4*)s_att)[fi];
                p[k] = fmaf(lrelu(v.x + x4.x), a4.x,
                       fmaf(lrelu(v.y + x4.y), a4.y,
                       fmaf(lrelu(v.z + x4.z), a4.z,
                            lrelu(v.w + x4.w) * a4.w)));
            }
            // block k covers heads {2k, 2k+1}: lane<16 -> 2k, lane>=16 -> 2k+1.
            // xor-reduce within each 16-lane half.
#pragma unroll
            for (int off = 1; off < 16; off <<= 1) {
#pragma unroll
                for (int k = 0; k < 4; k++)
                    p[k] += __shfl_xor_sync(0xffffffffu, p[k], off);
            }
            if (lane == 0)  { s_w[w][0] = p[0]; s_w[w][2] = p[1]; s_w[w][4] = p[2]; s_w[w][6] = p[3]; }
            if (lane == 16) { s_w[w][1] = p[0]; s_w[w][3] = p[1]; s_w[w][5] = p[2]; s_w[w][7] = p[3]; }
        }
        __syncthreads();
        if (t < H1) {                          // online softmax state update
            float m_old = s_m[t], cm = m_old;
            for (int j = 0; j < m_e; j++) cm = fmaxf(cm, s_w[j][t]);
            float sc = expf(m_old - cm);       // first chunk: exp(-inf)=0
            float d = s_den[t] * sc;
            for (int j = 0; j < m_e; j++) {
                float wj = expf(s_w[j][t] - cm);
                s_w[j][t] = wj;
                d += wj;
            }
            s_m[t] = cm; s_den[t] = d; s_scale[t] = sc;
        }
        __syncthreads();
        acc *= s_scale[h];
        for (int j = 0; j < m_e; j++)
            acc = fmaf(s_w[j][h], s_rows[j][t], acc);
        __syncthreads();                       // protect s_rows/s_w reuse
    }

    // epilogue: normalize, bias, relu; fused layer-2 projections + block reduce
    float r  = fmaxf(acc / s_den[h] + bias1[t], 0.0f);
    float pl = r * Wl2[t];
    float pr = r * Wr2[t];
#pragma unroll
    for (int off = 16; off > 0; off >>= 1) {
        pl += __shfl_down_sync(0xffffffffu, pl, off);
        pr += __shfl_down_sync(0xffffffffu, pr, off);
    }
    if (lane == 0) { s_rl[w] = pl; s_rr[w] = pr; }
    __syncthreads();
    if (t < 16) {
        pl = s_rl[t]; pr = s_rr[t];
#pragma unroll
        for (int off = 8; off > 0; off >>= 1) {
            pl += __shfl_down_sync(0x0000ffffu, pl, off);
            pr += __shfl_down_sync(0x0000ffffu, pr, off);
        }
        if (t == 0) {
            g_xl2[i] = pl + bl2[0];
            g_xr2[i] = pr + br2[0];
        }
    }
}

// ---------------- K5: fused layer-2 (warp = dst node) --------------------------
// Logits stored at CSR position j (coalesced) so pass 2 needs no eperm gather.
__global__ void k_l2(const int* __restrict__ ei,
                     const float* __restrict__ att2,
                     const float* __restrict__ bias2,
                     float* __restrict__ out) {
    int gw = (blockIdx.x * blockDim.x + threadIdx.x) >> 5;
    if (gw >= NN) return;
    int lane = threadIdx.x & 31;
    int i = gw;
    int start = g_rowptr[i], end = g_rowptr[i + 1];
    float a2 = att2[0];
    float xr = g_xr2[i];

    // pass 1: logits + warp max
    float m = -INFINITY;
    for (int j = start + lane; j < end; j += 32) {
        int e = g_eperm[j];
        float l = lrelu(g_xl2[srcof(ei, e)] + xr) * a2;
        g_l2[j] = l;
        m = fmaxf(m, l);
    }
#pragma unroll
    for (int off = 16; off > 0; off >>= 1)
        m = fmaxf(m, __shfl_xor_sync(0xffffffffu, m, off));

    // pass 2: denominator (coalesced)
    float den = 0.0f;
    for (int j = start + lane; j < end; j += 32)
        den += expf(g_l2[j] - m);
#pragma unroll
    for (int off = 16; off > 0; off >>= 1)
        den += __shfl_xor_sync(0xffffffffu, den, off);
    float invden = 1.0f / den;

    // pass 3: alpha out + weighted sum
    float acc = 0.0f;
    for (int j = start + lane; j < end; j += 32) {
        int e = g_eperm[j];
        float alpha = expf(g_l2[j] - m) * invden;
        out[NN + e] = alpha;
        acc = fmaf(alpha, g_xl2[srcof(ei, e)], acc);
    }
#pragma unroll
    for (int off = 16; off > 0; off >>= 1)
        acc += __shfl_xor_sync(0xffffffffu, acc, off);
    if (lane == 0) out[i] = acc + bias2[0];
}

// ---------------- launch ----------------
extern "C" void kernel_launch(void* const* d_in, const int* in_sizes, int n_in,
                              void* d_out, int out_size) {
    const float* x     = (const float*)d_in[0];
    const int*   ei    = (const int*)d_in[1];
    const float* Wl1   = (const float*)d_in[2];
    const float* bl1   = (const float*)d_in[3];
    const float* Wr1   = (const float*)d_in[4];
    const float* br1   = (const float*)d_in[5];
    const float* att1  = (const float*)d_in[6];
    const float* bias1 = (const float*)d_in[7];
    const float* Wl2   = (const float*)d_in[8];
    const float* bl2   = (const float*)d_in[9];
    const float* Wr2   = (const float*)d_in[10];
    const float* br2   = (const float*)d_in[11];
    const float* att2  = (const float*)d_in[12];
    const float* bias2 = (const float*)d_in[13];
    float* out = (float*)d_out;

    k_init0 <<<(NN + 255) / 256, 256>>>();
    k_degree<<<(EE + 255) / 256, 256>>>(ei);
    k_scan  <<<1, 1024>>>();
    k_scatter<<<(EE + 255) / 256, 256>>>(ei);
    k_lin1  <<<(NN + GN - 1) / GN, 512>>>(x, Wl1, bl1, Wr1, br1);
    k_fused1<<<NN, 512>>>(ei, att1, bias1, Wl2, bl2, Wr2, br2);
    k_l2    <<<(NN * 32 + 255) / 256, 256>>>(ei, att2, bias2, out);
}

// round 8
// speedup vs baseline: 1.6491x; 1.1663x over previous
#include <cuda_runtime.h>
#include <math.h>

#define NN 50000
#define EO 400000
#define EE 450000
#define F1 512
#define H1 8

// ---------------- scratch (device globals; no runtime allocation) ----------------
__device__ __align__(16) float g_xl1[(size_t)NN * F1];   // 102.4 MB
__device__ __align__(16) float g_xr1[(size_t)NN * F1];   // 102.4 MB
__device__ int   g_deg[NN];
__device__ int   g_rowptr[NN + 1];
__device__ int   g_cursor[NN];
__device__ int   g_eperm[EE];
__device__ float g_xl2[NN];
__device__ float g_xr2[NN];
__device__ float g_l2[EE];

__device__ __forceinline__ int srcof(const int* ei, int e) {
    return (e < EO) ? ei[e] : (e - EO);
}
__device__ __forceinline__ int dstof(const int* ei, int e) {
    return (e < EO) ? ei[EO + e] : (e - EO);
}
__device__ __forceinline__ float lrelu(float v) { return v > 0.0f ? v : 0.2f * v; }

// ---------------- K_init: zero degree histogram ----------------
__global__ void k_init0() {
    int t = blockIdx.x * blockDim.x + threadIdx.x;
    if (t < NN) g_deg[t] = 0;
}

// ---------------- K0: degree histogram ----------------
__global__ void k_degree(const int* __restrict__ ei) {
    int e = blockIdx.x * blockDim.x + threadIdx.x;
    if (e >= EE) return;
    atomicAdd(&g_deg[dstof(ei, e)], 1);
}

// ---------------- K1: thread-coarsened exclusive scan (rowptr + cursor) --------
__global__ void k_scan() {
    __shared__ int sh[1024];
    const int PER = (NN + 1023) / 1024;   // 49
    int t = threadIdx.x;
    int base = t * PER;
    int lim = (base < NN) ? min(PER, NN - base) : 0;
    int sum = 0;
    for (int k = 0; k < lim; k++) sum += g_deg[base + k];
    sh[t] = sum;
    __syncthreads();
    for (int off = 1; off < 1024; off <<= 1) {
        int add = (t >= off) ? sh[t - off] : 0;
        __syncthreads();
        sh[t] += add;
        __syncthreads();
    }
    int run = sh[t] - sum;                 // exclusive prefix of this segment
    for (int k = 0; k < lim; k++) {
        int v = g_deg[base + k];
        g_cursor[base + k] = run;
        run += v;
        g_rowptr[base + k + 1] = run;
    }
    if (t == 0) g_rowptr[0] = 0;
}

// ---------------- K2: scatter edge ids into CSR (dst-grouped) ----------------
__global__ void k_scatter(const int* __restrict__ ei) {
    int e = blockIdx.x * blockDim.x + threadIdx.x;
    if (e >= EE) return;
    int pos = atomicAdd(&g_cursor[dstof(ei, e)], 1);
    g_eperm[pos] = e;
}

// ---------------- K3: layer-1 linear transforms (64 nodes/block, W in regs) ----
#define GN 64
__global__ void __launch_bounds__(512) k_lin1(
    const float* __restrict__ x,
    const float* __restrict__ Wl, const float* __restrict__ bl,
    const float* __restrict__ Wr, const float* __restrict__ br) {
    __shared__ float xs[GN][24];
    int t = threadIdx.x;
    int n0 = blockIdx.x * GN;
    for (int idx = t; idx < GN * 23; idx += 512) {
        int n = idx / 23, k = idx % 23;
        int gi = n0 + n;
        xs[n][k] = (gi < NN) ? x[gi * 23 + k] : 0.0f;
    }
    float wl[23], wr[23];
#pragma unroll
    for (int k = 0; k < 23; k++) { wl[k] = Wl[k * F1 + t]; wr[k] = Wr[k * F1 + t]; }
    float bll = bl[t], brr = br[t];
    __syncthreads();
    for (int n = 0; n < GN; n++) {
        int gi = n0 + n;
        if (gi >= NN) break;
        float al = bll, ar = brr;
#pragma unroll
        for (int k = 0; k < 23; k++) {
            float xv = xs[n][k];
            al = fmaf(xv, wl[k], al);
            ar = fmaf(xv, wr[k], ar);
        }
        g_xl1[(size_t)gi * F1 + t] = al;
        g_xr1[(size_t)gi * F1 + t] = ar;
    }
}

// ---------------- K4: fused layer-1 attention (block = dst node, 256 thr) ------
// Phase 1: warps compute per-edge logits (no row staging). Phase 2: warp-per-head
// online softmax. Phase 3: aggregation re-gathers rows from global (L1-hot).
// Epilogue: bias+relu, fused layer-2 input projections -> g_xl2/g_xr2.
#define BT 256
#define CHF 32
__global__ void __launch_bounds__(BT) k_fused1(
    const int* __restrict__ ei,
    const float* __restrict__ att,
    const float* __restrict__ bias1,
    const float* __restrict__ Wl2, const float* __restrict__ bl2,
    const float* __restrict__ Wr2, const float* __restrict__ br2) {
    __shared__ float s_xr[F1];                 // 2 KB
    __shared__ float s_att[F1];                // 2 KB
    __shared__ float s_lg[CHF][9];             // logits -> weights (padded, 1.1 KB)
    __shared__ int   s_src[CHF];
    __shared__ float s_m[H1], s_den[H1], s_scale[H1];
    __shared__ float s_r1[8], s_r2[8];

    int i = blockIdx.x;
    int t = threadIdx.x;
    int w = t >> 5, lane = t & 31;
    int start = g_rowptr[i], end = g_rowptr[i + 1];

    s_xr[t]        = g_xr1[(size_t)i * F1 + t];
    s_xr[t + 256]  = g_xr1[(size_t)i * F1 + t + 256];
    s_att[t]       = att[t];
    s_att[t + 256] = att[t + 256];
    if (t < H1) { s_m[t] = -INFINITY; s_den[t] = 0.0f; }
    __syncthreads();

    int h0 = t >> 6;                           // head of feature t (0..3); t+256 -> h0+4
    float acc0 = 0.0f, acc1 = 0.0f;

    for (int c = start; c < end; c += CHF) {
        int m_e = min(CHF, end - c);

        // ---- phase 1: logits, warp per edge (strided by 8 warps) ----
        for (int le = w; le < m_e; le += 8) {
            int e = g_eperm[c + le];
            int s = srcof(ei, e);
            if (lane == 0) s_src[le] = s;
            const float4* prow = (const float4*)(g_xl1 + (size_t)s * F1);
            float p[4];
#pragma unroll
            for (int k = 0; k < 4; k++) {
                int fi = k * 32 + lane;
                float4 v  = prow[fi];
                float4 x4 = ((const float4*)s_xr)[fi];
                float4 a4 = ((const float4*)s_att)[fi];
                p[k] = fmaf(lrelu(v.x + x4.x), a4.x,
                       fmaf(lrelu(v.y + x4.y), a4.y,
                       fmaf(lrelu(v.z + x4.z), a4.z,
                            lrelu(v.w + x4.w) * a4.w)));
            }
            // block k covers heads {2k, 2k+1}: lanes<16 -> 2k, lanes>=16 -> 2k+1
#pragma unroll
            for (int off = 1; off < 16; off <<= 1) {
#pragma unroll
                for (int k = 0; k < 4; k++)
                    p[k] += __shfl_xor_sync(0xffffffffu, p[k], off);
            }
            if (lane == 0)  { s_lg[le][0] = p[0]; s_lg[le][2] = p[1]; s_lg[le][4] = p[2]; s_lg[le][6] = p[3]; }
            if (lane == 16) { s_lg[le][1] = p[0]; s_lg[le][3] = p[1]; s_lg[le][5] = p[2]; s_lg[le][7] = p[3]; }
        }
        __syncthreads();

        // ---- phase 2: online softmax, warp per head (all 8 warps busy) ----
        {
            float cm = -INFINITY;
            for (int j = lane; j < m_e; j += 32) cm = fmaxf(cm, s_lg[j][w]);
#pragma unroll
            for (int off = 16; off > 0; off >>= 1)
                cm = fmaxf(cm, __shfl_xor_sync(0xffffffffu, cm, off));
            float m_old = s_m[w];
            cm = fmaxf(cm, m_old);
            float dn = 0.0f;
            for (int j = lane; j < m_e; j += 32) {
                float wj = expf(s_lg[j][w] - cm);
                s_lg[j][w] = wj;
                dn += wj;
            }
#pragma unroll
            for (int off = 16; off > 0; off >>= 1)
                dn += __shfl_xor_sync(0xffffffffu, dn, off);
            if (lane == 0) {
                float sc = expf(m_old - cm);    // first chunk: exp(-inf)=0
                s_scale[w] = sc;
                s_den[w] = s_den[w] * sc + dn;
                s_m[w] = cm;
            }
        }
        __syncthreads();

        // ---- phase 3: aggregation, rows re-read from global (L1-hot) ----
        acc0 *= s_scale[h0];
        acc1 *= s_scale[h0 + 4];
        for (int j = 0; j < m_e; j++) {
            const float* row = g_xl1 + (size_t)s_src[j] * F1;
            acc0 = fmaf(s_lg[j][h0],     row[t],       acc0);
            acc1 = fmaf(s_lg[j][h0 + 4], row[t + 256], acc1);
        }
        __syncthreads();                       // protect s_lg/s_src reuse
    }

    // epilogue: normalize, bias, relu; fused layer-2 projections + block reduce
    float r0 = fmaxf(acc0 / s_den[h0]     + bias1[t],       0.0f);
    float r1 = fmaxf(acc1 / s_den[h0 + 4] + bias1[t + 256], 0.0f);
    float pl = fmaf(r0, Wl2[t], r1 * Wl2[t + 256]);
    float pr = fmaf(r0, Wr2[t], r1 * Wr2[t + 256]);
#pragma unroll
    for (int off = 16; off > 0; off >>= 1) {
        pl += __shfl_down_sync(0xffffffffu, pl, off);
        pr += __shfl_down_sync(0xffffffffu, pr, off);
    }
    if (lane == 0) { s_r1[w] = pl; s_r2[w] = pr; }
    __syncthreads();
    if (t < 8) {
        pl = s_r1[t]; pr = s_r2[t];
#pragma unroll
        for (int off = 4; off > 0; off >>= 1) {
            pl += __shfl_down_sync(0x000000ffu, pl, off);
            pr += __shfl_down_sync(0x000000ffu, pr, off);
        }
        if (t == 0) {
            g_xl2[i] = pl + bl2[0];
            g_xr2[i] = pr + br2[0];
        }
    }
}

// ---------------- K5: fused layer-2 (warp = dst node) --------------------------
// Logits stored at CSR position j (coalesced) so pass 2 needs no eperm gather.
__global__ void k_l2(const int* __restrict__ ei,
                     const float* __restrict__ att2,
                     const float* __restrict__ bias2,
                     float* __restrict__ out) {
    int gw = (blockIdx.x * blockDim.x + threadIdx.x) >> 5;
    if (gw >= NN) return;
    int lane = threadIdx.x & 31;
    int i = gw;
    int start = g_rowptr[i], end = g_rowptr[i + 1];
    float a2 = att2[0];
    float xr = g_xr2[i];

    // pass 1: logits + warp max
    float m = -INFINITY;
    for (int j = start + lane; j < end; j += 32) {
        int e = g_eperm[j];
        float l = lrelu(g_xl2[srcof(ei, e)] + xr) * a2;
        g_l2[j] = l;
        m = fmaxf(m, l);
    }
#pragma unroll
    for (int off = 16; off > 0; off >>= 1)
        m = fmaxf(m, __shfl_xor_sync(0xffffffffu, m, off));

    // pass 2: denominator (coalesced)
    float den = 0.0f;
    for (int j = start + lane; j < end; j += 32)
        den += expf(g_l2[j] - m);
#pragma unroll
    for (int off = 16; off > 0; off >>= 1)
        den += __shfl_xor_sync(0xffffffffu, den, off);
    float invden = 1.0f / den;

    // pass 3: alpha out + weighted sum
    float acc = 0.0f;
    for (int j = start + lane; j < end; j += 32) {
        int e = g_eperm[j];
        float alpha = expf(g_l2[j] - m) * invden;
        out[NN + e] = alpha;
        acc = fmaf(alpha, g_xl2[srcof(ei, e)], acc);
    }
#pragma unroll
    for (int off = 16; off > 0; off >>= 1)
        acc += __shfl_xor_sync(0xffffffffu, acc, off);
    if (lane == 0) out[i] = acc + bias2[0];
}

// ---------------- launch ----------------
extern "C" void kernel_launch(void* const* d_in, const int* in_sizes, int n_in,
                              void* d_out, int out_size) {
    const float* x     = (const float*)d_in[0];
    const int*   ei    = (const int*)d_in[1];
    const float* Wl1   = (const float*)d_in[2];
    const float* bl1   = (const float*)d_in[3];
    const float* Wr1   = (const float*)d_in[4];
    const float* br1   = (const float*)d_in[5];
    const float* att1  = (const float*)d_in[6];
    const float* bias1 = (const float*)d_in[7];
    const float* Wl2   = (const float*)d_in[8];
    const float* bl2   = (const float*)d_in[9];
    const float* Wr2   = (const float*)d_in[10];
    const float* br2   = (const float*)d_in[11];
    const float* att2  = (const float*)d_in[12];
    const float* bias2 = (const float*)d_in[13];
    float* out = (float*)d_out;

    k_init0 <<<(NN + 255) / 256, 256>>>();
    k_degree<<<(EE + 255) / 256, 256>>>(ei);
    k_scan  <<<1, 1024>>>();
    k_scatter<<<(EE + 255) / 256, 256>>>(ei);
    k_lin1  <<<(NN + GN - 1) / GN, 512>>>(x, Wl1, bl1, Wr1, br1);
    k_fused1<<<NN, BT>>>(ei, att1, bias1, Wl2, bl2, Wr2, br2);
    k_l2    <<<(NN * 32 + 255) / 256, 256>>>(ei, att2, bias2, out);
}